// round 8
// baseline (speedup 1.0000x reference)
#include <cuda_runtime.h>
#include <math.h>
#include <stdint.h>
#include <stddef.h>

// ============================================================================
// NoisyTopkRouter: fused bf16x3 (Ootomo) mma.sync GEMM + epilogue.
//   a = a1+a2+a3 (bf16 chunks, exact 24-bit split), same for b.
//   main acc:  a1*b1
//   corr acc:  a1*b2 + a2*b1 (2^-8) + a1*b3 + a2*b2 + a3*b1 (2^-16)
// R8: double-buffered smem planes, ONE __syncthreads per chunk (R7 had two
// with a serialized store phase -> tensor pipe idled ~50%).
// Output layout (validated): [route_p BS*E | ix-as-float BS*K | full_p BS*E]
// ============================================================================

#define E_FIX 64
#define NN    128         // outputs per token
#define MROWS 128         // tokens per CTA
#define KC    32          // K floats per chunk (= 2 k16 MMA steps)
#define NTHR  512
#define CS    132         // C-dump row stride (floats)

// smem planes: u32-packed bf16 pairs, row stride 20 u32 (80B) -> conflict-free
#define RS        20
#define PLANE_U32 (128 * RS)            // 2560 u32 = 10240 B
#define BUF_U32   (6 * PLANE_U32)       // 15360 u32 = 61440 B per buffer
#define SMEM_BYTES (2 * BUF_U32 * 4)    // 122880 B (C dump 67584 B reuses)

// pre-split B planes, chunk-major: [chunk][plane][row 128][col 16] u32
__device__ uint32_t g_Bp[32 * 3 * 128 * 16];   // 786 KB

typedef unsigned long long u64;

__device__ __forceinline__ uint32_t cvt2(float vhi, float vlo) {
    uint32_t u;
    asm("cvt.rn.bf16x2.f32 %0, %1, %2;" : "=r"(u) : "f"(vhi), "f"(vlo));
    return u;
}
__device__ __forceinline__ float lo_f(uint32_t u) { return __uint_as_float(u << 16); }
__device__ __forceinline__ float hi_f(uint32_t u) { return __uint_as_float(u & 0xFFFF0000u); }

// exact 3-way bf16 split of a float pair -> 3 packed u32
__device__ __forceinline__ void split3p(float vlo, float vhi,
                                        uint32_t& u1, uint32_t& u2, uint32_t& u3) {
    u1 = cvt2(vhi, vlo);
    float r1l = vlo - lo_f(u1), r1h = vhi - hi_f(u1);
    u2 = cvt2(r1h, r1l);
    float r2l = r1l - lo_f(u2), r2h = r1h - hi_f(u2);
    u3 = cvt2(r2h, r2l);
}

__device__ __forceinline__ void ldsm4(uint32_t* r, uint32_t addr) {
    asm volatile("ldmatrix.sync.aligned.m8n8.x4.shared.b16 {%0,%1,%2,%3}, [%4];"
                 : "=r"(r[0]), "=r"(r[1]), "=r"(r[2]), "=r"(r[3]) : "r"(addr));
}
__device__ __forceinline__ void mma_bf16(float* d, const uint32_t* a, const uint32_t* b) {
    asm("mma.sync.aligned.m16n8k16.row.col.f32.bf16.bf16.f32 "
        "{%0,%1,%2,%3}, {%4,%5,%6,%7}, {%8,%9}, {%0,%1,%2,%3};"
        : "+f"(d[0]), "+f"(d[1]), "+f"(d[2]), "+f"(d[3])
        : "r"(a[0]), "r"(a[1]), "r"(a[2]), "r"(a[3]), "r"(b[0]), "r"(b[1]));
}
__device__ __forceinline__ float softplus_f(float x) {
    return fmaxf(x, 0.0f) + log1pf(expf(-fabsf(x)));
}

// ---------------- pre-pass: split W rows into g_Bp planes -------------------
__global__ void __launch_bounds__(512)
bsplit_kernel(const float* __restrict__ Wl, const float* __restrict__ Wn, int D) {
    int idx = blockIdx.x * 512 + threadIdx.x;      // 0..65535 : (row, kpair)
    int row = idx >> 9;                            // 0..127
    int kp  = idx & 511;                           // pair index, k = 2*kp
    const float* W = (row < E_FIX) ? (Wl + (size_t)row * D)
                                   : (Wn + (size_t)(row - E_FIX) * D);
    float v0 = W[2 * kp], v1 = W[2 * kp + 1];
    uint32_t u1, u2, u3;
    split3p(v0, v1, u1, u2, u3);
    int chunk = kp >> 4, col = kp & 15;
    uint32_t* dst = g_Bp + (size_t)chunk * 6144 + row * 16 + col;
    dst[0]    = u1;
    dst[2048] = u2;
    dst[4096] = u3;
}

// ---------------- fused main kernel -----------------------------------------
__global__ void __launch_bounds__(NTHR)
router_fused(const float* __restrict__ h,
             const float* __restrict__ bl,
             const float* __restrict__ bn,
             const float* __restrict__ noise,
             float* __restrict__ out,
             int D, int BS, int K)
{
    extern __shared__ float sf[];
    uint32_t* su = (uint32_t*)sf;
    uint32_t smb;
    asm("{ .reg .u64 t; cvta.to.shared.u64 t, %1; cvt.u32.u64 %0, t; }" : "=r"(smb) : "l"(sf));

    const int tid  = threadIdx.x;
    const int wid  = tid >> 5;
    const int lane = tid & 31;
    const int g    = lane >> 2;
    const int t    = lane & 3;
    const int tokBase = blockIdx.x * MROWS;
    const int mbW = (wid & 3) * 32;      // warp m32 block
    const int nhW = (wid >> 2) * 32;     // warp n32 block

    // ldmatrix per-lane offsets (bytes within a plane) — validated R7 mapping
    const int ti = lane >> 3;
    const int a_off = (((ti & 1) * 8) + (lane & 7)) * 80 + ((ti >> 1) * 16);
    const int b_off = (((ti >> 1) * 8) + (lane & 7)) * 80 + ((ti & 1) * 16);

    // ---- producer assignments ----
    const int arow = tid >> 2, akq = tid & 3;
    const float* aptr = h + (size_t)(tokBase + arow) * D + akq * 8;
    const int a_su = arow * RS + akq * 4;          // u32 idx within a plane
    // B: 3 uint4 per thread; flat uint4 index f4 = tid + j*512 -> u32 f = 4*f4
    int b_pl[3], b_su[3];
#pragma unroll
    for (int j = 0; j < 3; ++j) {
        int f = (tid + j * 512) * 4;
        b_pl[j] = f >> 11;
        int rem = f & 2047;
        b_su[j] = (rem >> 4) * RS + (rem & 15);
    }

    float4 ra0, ra1; uint4 rbv[3];

    // ---- prologue: chunk 0 -> buffer 0 ----
    ra0 = *(const float4*)(aptr + 0);
    ra1 = *(const float4*)(aptr + 4);
#pragma unroll
    for (int j = 0; j < 3; ++j)
        rbv[j] = *((const uint4*)g_Bp + (tid + j * 512));
    {
        uint32_t p1[4], p2[4], p3[4];
        split3p(ra0.x, ra0.y, p1[0], p2[0], p3[0]);
        split3p(ra0.z, ra0.w, p1[1], p2[1], p3[1]);
        split3p(ra1.x, ra1.y, p1[2], p2[2], p3[2]);
        split3p(ra1.z, ra1.w, p1[3], p2[3], p3[3]);
        uint32_t* ab = su + a_su;
        *(uint4*)(ab + 0 * PLANE_U32) = make_uint4(p1[0], p1[1], p1[2], p1[3]);
        *(uint4*)(ab + 1 * PLANE_U32) = make_uint4(p2[0], p2[1], p2[2], p2[3]);
        *(uint4*)(ab + 2 * PLANE_U32) = make_uint4(p3[0], p3[1], p3[2], p3[3]);
#pragma unroll
        for (int j = 0; j < 3; ++j)
            *(uint4*)(su + 3 * PLANE_U32 + b_pl[j] * PLANE_U32 + b_su[j]) = rbv[j];
    }
    __syncthreads();

    float accM[2][4][4], accC[2][4][4];
#pragma unroll
    for (int mt = 0; mt < 2; ++mt)
#pragma unroll
        for (int nt = 0; nt < 4; ++nt)
#pragma unroll
            for (int j = 0; j < 4; ++j) { accM[mt][nt][j] = 0.f; accC[mt][nt][j] = 0.f; }

    const int NCH = D / KC;   // 32
    for (int s = 0; s < NCH; ++s) {
        const bool more = (s + 1) < NCH;
        if (more) {
            const int off = (s + 1) * KC;
            ra0 = *(const float4*)(aptr + off);
            ra1 = *(const float4*)(aptr + off + 4);
            const uint4* bp = (const uint4*)(g_Bp + (size_t)(s + 1) * 6144);
#pragma unroll
            for (int j = 0; j < 3; ++j) rbv[j] = bp[tid + j * 512];
        }

        // ---- consume buffer s&1 (MMA), overlapped with other warps' stores ----
        const uint32_t abase = smb + (s & 1) * (BUF_U32 * 4);
        const uint32_t bbase = abase + 3 * PLANE_U32 * 4;
#pragma unroll
        for (int kb = 0; kb < 2; ++kb) {
            uint32_t aa[3][2][4];
#pragma unroll
            for (int p = 0; p < 3; ++p)
#pragma unroll
                for (int mt = 0; mt < 2; ++mt)
                    ldsm4(aa[p][mt],
                          abase + p * 10240 + (mbW + mt * 16) * 80 + kb * 32 + a_off);
#pragma unroll
            for (int bt = 0; bt < 2; ++bt) {
                uint32_t bb[3][4];
#pragma unroll
                for (int p = 0; p < 3; ++p)
                    ldsm4(bb[p],
                          bbase + p * 10240 + (nhW + bt * 16) * 80 + kb * 32 + b_off);
#pragma unroll
                for (int mt = 0; mt < 2; ++mt)
#pragma unroll
                    for (int j = 0; j < 2; ++j) {      // nt = bt*2 + j
                        const int nt = bt * 2 + j;
                        const uint32_t* b1 = bb[0] + 2 * j;
                        const uint32_t* b2 = bb[1] + 2 * j;
                        const uint32_t* b3 = bb[2] + 2 * j;
                        mma_bf16(accM[mt][nt], aa[0][mt], b1);
                        mma_bf16(accC[mt][nt], aa[0][mt], b2);
                        mma_bf16(accC[mt][nt], aa[1][mt], b1);
                        mma_bf16(accC[mt][nt], aa[0][mt], b3);
                        mma_bf16(accC[mt][nt], aa[1][mt], b2);
                        mma_bf16(accC[mt][nt], aa[2][mt], b1);
                    }
            }
        }

        // ---- split + store chunk s+1 into the other buffer (no pre-barrier:
        //      that buffer was consumed at iter s-1; sync below published it) ----
        if (more) {
            uint32_t* dbuf = su + ((s + 1) & 1) * BUF_U32;
            uint32_t p1[4], p2[4], p3[4];
            split3p(ra0.x, ra0.y, p1[0], p2[0], p3[0]);
            split3p(ra0.z, ra0.w, p1[1], p2[1], p3[1]);
            split3p(ra1.x, ra1.y, p1[2], p2[2], p3[2]);
            split3p(ra1.z, ra1.w, p1[3], p2[3], p3[3]);
            uint32_t* ab = dbuf + a_su;
            *(uint4*)(ab + 0 * PLANE_U32) = make_uint4(p1[0], p1[1], p1[2], p1[3]);
            *(uint4*)(ab + 1 * PLANE_U32) = make_uint4(p2[0], p2[1], p2[2], p2[3]);
            *(uint4*)(ab + 2 * PLANE_U32) = make_uint4(p3[0], p3[1], p3[2], p3[3]);
#pragma unroll
            for (int j = 0; j < 3; ++j)
                *(uint4*)(dbuf + 3 * PLANE_U32 + b_pl[j] * PLANE_U32 + b_su[j]) = rbv[j];
        }
        __syncthreads();
    }

    // ---- merge + dump C to smem (reuses plane region) ----
#pragma unroll
    for (int mt = 0; mt < 2; ++mt)
#pragma unroll
        for (int nt = 0; nt < 4; ++nt) {
            const int r0 = mbW + mt * 16 + g;
            const int c  = nhW + nt * 8 + 2 * t;
            *(float2*)&sf[r0 * CS + c] =
                make_float2(accM[mt][nt][0] + accC[mt][nt][0],
                            accM[mt][nt][1] + accC[mt][nt][1]);
            *(float2*)&sf[(r0 + 8) * CS + c] =
                make_float2(accM[mt][nt][2] + accC[mt][nt][2],
                            accM[mt][nt][3] + accC[mt][nt][3]);
        }
    __syncthreads();

    // ---- epilogue: thread tid<128 handles token tokBase+tid (validated) ----
    if (tid < MROWS) {
        const int tok = tokBase + tid;
        const float* pre = sf + tid * CS;
        const float* nzr = noise + (size_t)tok * E_FIX;

        float noisy[E_FIX];
#pragma unroll
        for (int q = 0; q < E_FIX / 4; ++q) {
            float4 lg = *(const float4*)(pre + 4 * q);
            float4 np = *(const float4*)(pre + E_FIX + 4 * q);
            float4 nv = *(const float4*)(nzr + 4 * q);
            float4 b0 = *(const float4*)(bl + 4 * q);
            float4 b1 = *(const float4*)(bn + 4 * q);
            noisy[4*q+0] = lg.x + b0.x + nv.x * softplus_f(np.x + b1.x);
            noisy[4*q+1] = lg.y + b0.y + nv.y * softplus_f(np.y + b1.y);
            noisy[4*q+2] = lg.z + b0.z + nv.z * softplus_f(np.z + b1.z);
            noisy[4*q+3] = lg.w + b0.w + nv.w * softplus_f(np.w + b1.w);
        }

        float m = noisy[0];
#pragma unroll
        for (int e = 1; e < E_FIX; ++e) m = fmaxf(m, noisy[e]);

        int kidx[8]; float kval[8];
        u64 chosen = 0ull;
        for (int j = 0; j < K; ++j) {
            float best = -INFINITY; int bi = 0;
#pragma unroll
            for (int e = 0; e < E_FIX; ++e) {
                bool ok = (((chosen >> e) & 1ull) == 0ull) && (noisy[e] > best);
                best = ok ? noisy[e] : best;
                bi   = ok ? e : bi;
            }
            kidx[j] = bi; kval[j] = best;
            chosen |= (1ull << bi);
        }

        float sum = 0.0f;
#pragma unroll
        for (int e = 0; e < E_FIX; ++e) { float x = expf(noisy[e] - m); noisy[e] = x; sum += x; }
        const float inv = 1.0f / sum;

        float* route = out + (size_t)tok * E_FIX;
        float* ixo   = out + (size_t)BS * E_FIX + (size_t)tok * K;
        float* fullp = out + (size_t)BS * (E_FIX + K) + (size_t)tok * E_FIX;
#pragma unroll
        for (int q = 0; q < 16; ++q) *(float4*)(route + 4 * q) = make_float4(0.f, 0.f, 0.f, 0.f);
#pragma unroll
        for (int q = 0; q < 16; ++q)
            *(float4*)(fullp + 4 * q) = make_float4(noisy[4*q+0] * inv, noisy[4*q+1] * inv,
                                                    noisy[4*q+2] * inv, noisy[4*q+3] * inv);
        const float rm = kval[0];
        float rs = 0.0f, rv[8];
        for (int j = 0; j < K; ++j) { rv[j] = expf(kval[j] - rm); rs += rv[j]; }
        const float rinv = 1.0f / rs;
        for (int j = 0; j < K; ++j) { route[kidx[j]] = rv[j] * rinv; ixo[j] = (float)kidx[j]; }
    }
}

// ----------------------------------------------------------------------------
// Inputs (metadata order): h, Wl, bl, Wn, bn, noise, [top_k]
// ----------------------------------------------------------------------------
extern "C" void kernel_launch(void* const* d_in, const int* in_sizes, int n_in,
                              void* d_out, int out_size) {
    const float* h  = (const float*)d_in[0];
    const float* Wl = (const float*)d_in[1];
    const float* bl = (const float*)d_in[2];
    const float* Wn = (const float*)d_in[3];
    const float* bn = (const float*)d_in[4];
    const float* nz = (const float*)d_in[5];

    const int E = in_sizes[2];                     // 64
    const int D = in_sizes[1] / E;                 // 1024
    const long long BSE = (long long)in_sizes[5];  // B*S*E
    const int BS = (int)(BSE / E);                 // 32768

    int K = (int)(((long long)out_size - 2LL * BSE) / (long long)BS);
    if (K < 1 || K > 8) K = 2;

    bsplit_kernel<<<128, 512>>>(Wl, Wn, D);
    cudaFuncSetAttribute(router_fused, cudaFuncAttributeMaxDynamicSharedMemorySize, SMEM_BYTES);
    router_fused<<<BS / MROWS, NTHR, SMEM_BYTES>>>(h, bl, bn, nz, (float*)d_out, D, BS, K);
}

// round 9
// speedup vs baseline: 1.0758x; 1.0758x over previous
#include <cuda_runtime.h>
#include <math.h>
#include <stdint.h>
#include <stddef.h>

// ============================================================================
// NoisyTopkRouter: fused bf16x3 (Ootomo) mma.sync GEMM + epilogue.
//   a = a1+a2+a3 (bf16 chunks, exact 24-bit split), same for b.
//   main acc:  a1*b1
//   corr acc:  a1*b2 + a2*b1 (2^-8) + a1*b3 + a2*b2 + a3*b1 (2^-16)
// R9: 256-thread CTAs (MROWS=64), 2 CTAs/SM -> inter-CTA overlap hides the
// produce/barrier phases that idled the tensor pipe at occupancy 1 (R7/R8).
// R7-proven single-buffer, two-barrier chunk loop; B goes L2->smem in the
// produce phase (no reg prefetch; co-resident CTA covers the L2 latency).
// Output layout (validated): [route_p BS*E | ix-as-float BS*K | full_p BS*E]
// ============================================================================

#define E_FIX 64
#define NN    128         // outputs per token
#define MROWS 64          // tokens per CTA
#define KC    32          // K floats per chunk (= 2 k16 MMA steps)
#define NTHR  256
#define CS    132         // C-dump row stride (floats)

// smem planes: u32-packed bf16 pairs, row stride 20 u32 (80B)
#define RS        20
#define A_PLANE_U32 (MROWS * RS)        // 1280 u32 = 5120 B
#define B_PLANE_U32 (128 * RS)          // 2560 u32 = 10240 B
#define B_BASE_U32  (3 * A_PLANE_U32)   // 3840
#define SMEM_U32    (B_BASE_U32 + 3 * B_PLANE_U32)   // 11520 u32 = 46080 B
#define SMEM_BYTES  (SMEM_U32 * 4)      // C dump 64*132*4 = 33792 B reuses

// pre-split B planes, chunk-major: [chunk][plane][row 128][col 16] u32
__device__ uint32_t g_Bp[32 * 3 * 128 * 16];   // 786 KB

typedef unsigned long long u64;

__device__ __forceinline__ uint32_t cvt2(float vhi, float vlo) {
    uint32_t u;
    asm("cvt.rn.bf16x2.f32 %0, %1, %2;" : "=r"(u) : "f"(vhi), "f"(vlo));
    return u;
}
__device__ __forceinline__ float lo_f(uint32_t u) { return __uint_as_float(u << 16); }
__device__ __forceinline__ float hi_f(uint32_t u) { return __uint_as_float(u & 0xFFFF0000u); }

// exact 3-way bf16 split of a float pair -> 3 packed u32
__device__ __forceinline__ void split3p(float vlo, float vhi,
                                        uint32_t& u1, uint32_t& u2, uint32_t& u3) {
    u1 = cvt2(vhi, vlo);
    float r1l = vlo - lo_f(u1), r1h = vhi - hi_f(u1);
    u2 = cvt2(r1h, r1l);
    float r2l = r1l - lo_f(u2), r2h = r1h - hi_f(u2);
    u3 = cvt2(r2h, r2l);
}

__device__ __forceinline__ void ldsm4(uint32_t* r, uint32_t addr) {
    asm volatile("ldmatrix.sync.aligned.m8n8.x4.shared.b16 {%0,%1,%2,%3}, [%4];"
                 : "=r"(r[0]), "=r"(r[1]), "=r"(r[2]), "=r"(r[3]) : "r"(addr));
}
__device__ __forceinline__ void mma_bf16(float* d, const uint32_t* a, const uint32_t* b) {
    asm("mma.sync.aligned.m16n8k16.row.col.f32.bf16.bf16.f32 "
        "{%0,%1,%2,%3}, {%4,%5,%6,%7}, {%8,%9}, {%0,%1,%2,%3};"
        : "+f"(d[0]), "+f"(d[1]), "+f"(d[2]), "+f"(d[3])
        : "r"(a[0]), "r"(a[1]), "r"(a[2]), "r"(a[3]), "r"(b[0]), "r"(b[1]));
}
__device__ __forceinline__ float softplus_f(float x) {
    return fmaxf(x, 0.0f) + log1pf(expf(-fabsf(x)));
}

// ---------------- pre-pass: split W rows into g_Bp planes -------------------
__global__ void __launch_bounds__(512)
bsplit_kernel(const float* __restrict__ Wl, const float* __restrict__ Wn, int D) {
    int idx = blockIdx.x * 512 + threadIdx.x;      // 0..65535 : (row, kpair)
    int row = idx >> 9;                            // 0..127
    int kp  = idx & 511;                           // pair index, k = 2*kp
    const float* W = (row < E_FIX) ? (Wl + (size_t)row * D)
                                   : (Wn + (size_t)(row - E_FIX) * D);
    float v0 = W[2 * kp], v1 = W[2 * kp + 1];
    uint32_t u1, u2, u3;
    split3p(v0, v1, u1, u2, u3);
    int chunk = kp >> 4, col = kp & 15;
    uint32_t* dst = g_Bp + (size_t)chunk * 6144 + row * 16 + col;
    dst[0]    = u1;
    dst[2048] = u2;
    dst[4096] = u3;
}

// ---------------- fused main kernel -----------------------------------------
__global__ void __launch_bounds__(NTHR, 2)
router_fused(const float* __restrict__ h,
             const float* __restrict__ bl,
             const float* __restrict__ bn,
             const float* __restrict__ noise,
             float* __restrict__ out,
             int D, int BS, int K)
{
    extern __shared__ float sf[];
    uint32_t* su = (uint32_t*)sf;
    uint32_t smb;
    asm("{ .reg .u64 t; cvta.to.shared.u64 t, %1; cvt.u32.u64 %0, t; }" : "=r"(smb) : "l"(sf));

    const int tid  = threadIdx.x;
    const int wid  = tid >> 5;
    const int lane = tid & 31;
    const int g    = lane >> 2;
    const int t    = lane & 3;
    const int tokBase = blockIdx.x * MROWS;
    const int mbW = (wid & 1) * 32;      // warp m32 block (64 rows / 2)
    const int nhW = (wid >> 1) * 32;     // warp n32 block (128 cols / 4)

    // ldmatrix per-lane offsets (bytes within a plane) — validated R7 mapping
    const int ti = lane >> 3;
    const int a_off = (((ti & 1) * 8) + (lane & 7)) * 80 + ((ti >> 1) * 16);
    const int b_off = (((ti >> 1) * 8) + (lane & 7)) * 80 + ((ti & 1) * 16);

    // ---- producer assignments ----
    // A: thread -> (row = tid>>2, kq = tid&3): 8 floats at k = kq*8
    const int arow = tid >> 2, akq = tid & 3;
    const float* aptr = h + (size_t)(tokBase + arow) * D + akq * 8;
    const int a_su = arow * RS + akq * 4;          // u32 idx within a plane
    // B: 6 uint4 per thread; flat uint4 index f4 = tid + j*256 -> u32 f = 4*f4
    int b_pl[6], b_su[6];
#pragma unroll
    for (int j = 0; j < 6; ++j) {
        int f = (tid + j * NTHR) * 4;
        b_pl[j] = f >> 11;
        int rem = f & 2047;
        b_su[j] = (rem >> 4) * RS + (rem & 15);
    }

    float4 ra0, ra1;

    // ---- prologue: chunk 0 ----
    ra0 = *(const float4*)(aptr + 0);
    ra1 = *(const float4*)(aptr + 4);
    {
        uint32_t p1[4], p2[4], p3[4];
        split3p(ra0.x, ra0.y, p1[0], p2[0], p3[0]);
        split3p(ra0.z, ra0.w, p1[1], p2[1], p3[1]);
        split3p(ra1.x, ra1.y, p1[2], p2[2], p3[2]);
        split3p(ra1.z, ra1.w, p1[3], p2[3], p3[3]);
        uint32_t* ab = su + a_su;
        *(uint4*)(ab + 0 * A_PLANE_U32) = make_uint4(p1[0], p1[1], p1[2], p1[3]);
        *(uint4*)(ab + 1 * A_PLANE_U32) = make_uint4(p2[0], p2[1], p2[2], p2[3]);
        *(uint4*)(ab + 2 * A_PLANE_U32) = make_uint4(p3[0], p3[1], p3[2], p3[3]);
        const uint4* bp = (const uint4*)g_Bp;
#pragma unroll
        for (int j = 0; j < 6; ++j) {
            uint4 v = bp[tid + j * NTHR];
            *(uint4*)(su + B_BASE_U32 + b_pl[j] * B_PLANE_U32 + b_su[j]) = v;
        }
    }
    __syncthreads();

    float accM[2][4][4], accC[2][4][4];
#pragma unroll
    for (int mt = 0; mt < 2; ++mt)
#pragma unroll
        for (int nt = 0; nt < 4; ++nt)
#pragma unroll
            for (int j = 0; j < 4; ++j) { accM[mt][nt][j] = 0.f; accC[mt][nt][j] = 0.f; }

    const int NCH = D / KC;   // 32
    for (int s = 0; s < NCH; ++s) {
        const bool more = (s + 1) < NCH;
        if (more) {                       // A prefetch only (8 regs)
            const int off = (s + 1) * KC;
            ra0 = *(const float4*)(aptr + off);
            ra1 = *(const float4*)(aptr + off + 4);
        }

        // ---- consume: 2 k16 steps (overlaps co-resident CTA's produce) ----
#pragma unroll
        for (int kb = 0; kb < 2; ++kb) {
            uint32_t aa[3][2][4];
#pragma unroll
            for (int p = 0; p < 3; ++p)
#pragma unroll
                for (int mt = 0; mt < 2; ++mt)
                    ldsm4(aa[p][mt],
                          smb + p * (A_PLANE_U32 * 4) + (mbW + mt * 16) * 80 + kb * 32 + a_off);
#pragma unroll
            for (int bt = 0; bt < 2; ++bt) {
                uint32_t bb[3][4];
#pragma unroll
                for (int p = 0; p < 3; ++p)
                    ldsm4(bb[p],
                          smb + B_BASE_U32 * 4 + p * (B_PLANE_U32 * 4)
                              + (nhW + bt * 16) * 80 + kb * 32 + b_off);
#pragma unroll
                for (int mt = 0; mt < 2; ++mt)
#pragma unroll
                    for (int j = 0; j < 2; ++j) {      // nt = bt*2 + j
                        const int nt = bt * 2 + j;
                        const uint32_t* b1 = bb[0] + 2 * j;
                        const uint32_t* b2 = bb[1] + 2 * j;
                        const uint32_t* b3 = bb[2] + 2 * j;
                        mma_bf16(accM[mt][nt], aa[0][mt], b1);
                        mma_bf16(accC[mt][nt], aa[0][mt], b2);
                        mma_bf16(accC[mt][nt], aa[1][mt], b1);
                        mma_bf16(accC[mt][nt], aa[0][mt], b3);
                        mma_bf16(accC[mt][nt], aa[1][mt], b2);
                        mma_bf16(accC[mt][nt], aa[2][mt], b1);
                    }
            }
        }
        __syncthreads();

        // ---- produce chunk s+1: A from prefetched regs, B direct L2->smem ----
        if (more) {
            uint32_t p1[4], p2[4], p3[4];
            split3p(ra0.x, ra0.y, p1[0], p2[0], p3[0]);
            split3p(ra0.z, ra0.w, p1[1], p2[1], p3[1]);
            split3p(ra1.x, ra1.y, p1[2], p2[2], p3[2]);
            split3p(ra1.z, ra1.w, p1[3], p2[3], p3[3]);
            uint32_t* ab = su + a_su;
            *(uint4*)(ab + 0 * A_PLANE_U32) = make_uint4(p1[0], p1[1], p1[2], p1[3]);
            *(uint4*)(ab + 1 * A_PLANE_U32) = make_uint4(p2[0], p2[1], p2[2], p2[3]);
            *(uint4*)(ab + 2 * A_PLANE_U32) = make_uint4(p3[0], p3[1], p3[2], p3[3]);
            const uint4* bp = (const uint4*)(g_Bp + (size_t)(s + 1) * 6144);
#pragma unroll
            for (int j = 0; j < 6; ++j) {
                uint4 v = bp[tid + j * NTHR];
                *(uint4*)(su + B_BASE_U32 + b_pl[j] * B_PLANE_U32 + b_su[j]) = v;
            }
            __syncthreads();
        }
    }

    // ---- merge + dump C to smem (reuses plane region) ----
    __syncthreads();
#pragma unroll
    for (int mt = 0; mt < 2; ++mt)
#pragma unroll
        for (int nt = 0; nt < 4; ++nt) {
            const int r0 = mbW + mt * 16 + g;
            const int c  = nhW + nt * 8 + 2 * t;
            *(float2*)&sf[r0 * CS + c] =
                make_float2(accM[mt][nt][0] + accC[mt][nt][0],
                            accM[mt][nt][1] + accC[mt][nt][1]);
            *(float2*)&sf[(r0 + 8) * CS + c] =
                make_float2(accM[mt][nt][2] + accC[mt][nt][2],
                            accM[mt][nt][3] + accC[mt][nt][3]);
        }
    __syncthreads();

    // ---- epilogue: thread tid<64 handles token tokBase+tid (validated) ----
    if (tid < MROWS) {
        const int tok = tokBase + tid;
        const float* pre = sf + tid * CS;
        const float* nzr = noise + (size_t)tok * E_FIX;

        float noisy[E_FIX];
#pragma unroll
        for (int q = 0; q < E_FIX / 4; ++q) {
            float4 lg = *(const float4*)(pre + 4 * q);
            float4 np = *(const float4*)(pre + E_FIX + 4 * q);
            float4 nv = *(const float4*)(nzr + 4 * q);
            float4 b0 = *(const float4*)(bl + 4 * q);
            float4 b1 = *(const float4*)(bn + 4 * q);
            noisy[4*q+0] = lg.x + b0.x + nv.x * softplus_f(np.x + b1.x);
            noisy[4*q+1] = lg.y + b0.y + nv.y * softplus_f(np.y + b1.y);
            noisy[4*q+2] = lg.z + b0.z + nv.z * softplus_f(np.z + b1.z);
            noisy[4*q+3] = lg.w + b0.w + nv.w * softplus_f(np.w + b1.w);
        }

        float m = noisy[0];
#pragma unroll
        for (int e = 1; e < E_FIX; ++e) m = fmaxf(m, noisy[e]);

        int kidx[8]; float kval[8];
        u64 chosen = 0ull;
        for (int j = 0; j < K; ++j) {
            float best = -INFINITY; int bi = 0;
#pragma unroll
            for (int e = 0; e < E_FIX; ++e) {
                bool ok = (((chosen >> e) & 1ull) == 0ull) && (noisy[e] > best);
                best = ok ? noisy[e] : best;
                bi   = ok ? e : bi;
            }
            kidx[j] = bi; kval[j] = best;
            chosen |= (1ull << bi);
        }

        float sum = 0.0f;
#pragma unroll
        for (int e = 0; e < E_FIX; ++e) { float x = expf(noisy[e] - m); noisy[e] = x; sum += x; }
        const float inv = 1.0f / sum;

        float* route = out + (size_t)tok * E_FIX;
        float* ixo   = out + (size_t)BS * E_FIX + (size_t)tok * K;
        float* fullp = out + (size_t)BS * (E_FIX + K) + (size_t)tok * E_FIX;
#pragma unroll
        for (int q = 0; q < 16; ++q) *(float4*)(route + 4 * q) = make_float4(0.f, 0.f, 0.f, 0.f);
#pragma unroll
        for (int q = 0; q < 16; ++q)
            *(float4*)(fullp + 4 * q) = make_float4(noisy[4*q+0] * inv, noisy[4*q+1] * inv,
                                                    noisy[4*q+2] * inv, noisy[4*q+3] * inv);
        const float rm = kval[0];
        float rs = 0.0f, rv[8];
        for (int j = 0; j < K; ++j) { rv[j] = expf(kval[j] - rm); rs += rv[j]; }
        const float rinv = 1.0f / rs;
        for (int j = 0; j < K; ++j) { route[kidx[j]] = rv[j] * rinv; ixo[j] = (float)kidx[j]; }
    }
}

// ----------------------------------------------------------------------------
// Inputs (metadata order): h, Wl, bl, Wn, bn, noise, [top_k]
// ----------------------------------------------------------------------------
extern "C" void kernel_launch(void* const* d_in, const int* in_sizes, int n_in,
                              void* d_out, int out_size) {
    const float* h  = (const float*)d_in[0];
    const float* Wl = (const float*)d_in[1];
    const float* bl = (const float*)d_in[2];
    const float* Wn = (const float*)d_in[3];
    const float* bn = (const float*)d_in[4];
    const float* nz = (const float*)d_in[5];

    const int E = in_sizes[2];                     // 64
    const int D = in_sizes[1] / E;                 // 1024
    const long long BSE = (long long)in_sizes[5];  // B*S*E
    const int BS = (int)(BSE / E);                 // 32768

    int K = (int)(((long long)out_size - 2LL * BSE) / (long long)BS);
    if (K < 1 || K > 8) K = 2;

    bsplit_kernel<<<128, 512>>>(Wl, Wn, D);
    cudaFuncSetAttribute(router_fused, cudaFuncAttributeMaxDynamicSharedMemorySize, SMEM_BYTES);
    router_fused<<<BS / MROWS, NTHR, SMEM_BYTES>>>(h, bl, bn, nz, (float*)d_out, D, BS, K);
}

// round 10
// speedup vs baseline: 1.1362x; 1.0562x over previous
#include <cuda_runtime.h>
#include <math.h>
#include <stdint.h>
#include <stddef.h>

// ============================================================================
// NoisyTopkRouter: fused bf16x3 (Ootomo) mma.sync GEMM + epilogue.
//   a = a1+a2+a3 (bf16 chunks, exact 24-bit split), same for b.
//   main acc:  a1*b1
//   corr acc:  a1*b2 + a2*b1 (2^-8) + a1*b3 + a2*b2 + a3*b1 (2^-16)
// R10 = R7 (best, 180us) + term-major MMA ordering: the 5 accC updates per
// (mt,nt) were back-to-back RAW-dependent HMMAs (chain depth 5) -> warps
// stalled on HMMA latency, tensor pipe stuck ~46%. Now each accC reuse is
// 8 independent MMAs apart. B reg-prefetch dropped (R9-validated direct
// L2->smem produce) to keep regs ~128.
// Output layout (validated): [route_p BS*E | ix-as-float BS*K | full_p BS*E]
// ============================================================================

#define E_FIX 64
#define NN    128         // outputs per token
#define MROWS 128         // tokens per CTA
#define KC    32          // K floats per chunk (= 2 k16 MMA steps)
#define NTHR  512
#define CS    132         // C-dump row stride (floats)

// smem planes: u32-packed bf16 pairs, row stride 20 u32 (80B) -> conflict-free
#define RS        20
#define PLANE_U32 (128 * RS)            // 2560 u32 = 10240 B
#define B_BASE_B  (3 * PLANE_U32 * 4)   // 30720
#define SMEM_BYTES 69632                // max(planes 61440, C dump 128*132*4)

// pre-split B planes, chunk-major: [chunk][plane][row 128][col 16] u32
__device__ uint32_t g_Bp[32 * 3 * 128 * 16];   // 786 KB

typedef unsigned long long u64;

__device__ __forceinline__ uint32_t cvt2(float vhi, float vlo) {
    uint32_t u;
    asm("cvt.rn.bf16x2.f32 %0, %1, %2;" : "=r"(u) : "f"(vhi), "f"(vlo));
    return u;
}
__device__ __forceinline__ float lo_f(uint32_t u) { return __uint_as_float(u << 16); }
__device__ __forceinline__ float hi_f(uint32_t u) { return __uint_as_float(u & 0xFFFF0000u); }

// exact 3-way bf16 split of a float pair -> 3 packed u32
__device__ __forceinline__ void split3p(float vlo, float vhi,
                                        uint32_t& u1, uint32_t& u2, uint32_t& u3) {
    u1 = cvt2(vhi, vlo);
    float r1l = vlo - lo_f(u1), r1h = vhi - hi_f(u1);
    u2 = cvt2(r1h, r1l);
    float r2l = r1l - lo_f(u2), r2h = r1h - hi_f(u2);
    u3 = cvt2(r2h, r2l);
}

__device__ __forceinline__ void ldsm4(uint32_t* r, uint32_t addr) {
    asm volatile("ldmatrix.sync.aligned.m8n8.x4.shared.b16 {%0,%1,%2,%3}, [%4];"
                 : "=r"(r[0]), "=r"(r[1]), "=r"(r[2]), "=r"(r[3]) : "r"(addr));
}
__device__ __forceinline__ void mma_bf16(float* d, const uint32_t* a, const uint32_t* b) {
    asm("mma.sync.aligned.m16n8k16.row.col.f32.bf16.bf16.f32 "
        "{%0,%1,%2,%3}, {%4,%5,%6,%7}, {%8,%9}, {%0,%1,%2,%3};"
        : "+f"(d[0]), "+f"(d[1]), "+f"(d[2]), "+f"(d[3])
        : "r"(a[0]), "r"(a[1]), "r"(a[2]), "r"(a[3]), "r"(b[0]), "r"(b[1]));
}
__device__ __forceinline__ float softplus_f(float x) {
    return fmaxf(x, 0.0f) + log1pf(expf(-fabsf(x)));
}

// ---------------- pre-pass: split W rows into g_Bp planes -------------------
__global__ void __launch_bounds__(512)
bsplit_kernel(const float* __restrict__ Wl, const float* __restrict__ Wn, int D) {
    int idx = blockIdx.x * 512 + threadIdx.x;      // 0..65535 : (row, kpair)
    int row = idx >> 9;                            // 0..127
    int kp  = idx & 511;                           // pair index, k = 2*kp
    const float* W = (row < E_FIX) ? (Wl + (size_t)row * D)
                                   : (Wn + (size_t)(row - E_FIX) * D);
    float v0 = W[2 * kp], v1 = W[2 * kp + 1];
    uint32_t u1, u2, u3;
    split3p(v0, v1, u1, u2, u3);
    int chunk = kp >> 4, col = kp & 15;
    uint32_t* dst = g_Bp + (size_t)chunk * 6144 + row * 16 + col;
    dst[0]    = u1;
    dst[2048] = u2;
    dst[4096] = u3;
}

// ---------------- fused main kernel -----------------------------------------
__global__ void __launch_bounds__(NTHR)
router_fused(const float* __restrict__ h,
             const float* __restrict__ bl,
             const float* __restrict__ bn,
             const float* __restrict__ noise,
             float* __restrict__ out,
             int D, int BS, int K)
{
    extern __shared__ float sf[];
    uint32_t* su = (uint32_t*)sf;
    uint32_t smb;
    asm("{ .reg .u64 t; cvta.to.shared.u64 t, %1; cvt.u32.u64 %0, t; }" : "=r"(smb) : "l"(sf));

    const int tid  = threadIdx.x;
    const int wid  = tid >> 5;
    const int lane = tid & 31;
    const int g    = lane >> 2;
    const int t    = lane & 3;
    const int tokBase = blockIdx.x * MROWS;
    const int mbW = (wid & 3) * 32;      // warp m32 block
    const int nhW = (wid >> 2) * 32;     // warp n32 block

    // ldmatrix per-lane offsets (bytes within a plane) — validated R7 mapping
    const int ti = lane >> 3;
    const int a_off = (((ti & 1) * 8) + (lane & 7)) * 80 + ((ti >> 1) * 16);
    const int b_off = (((ti >> 1) * 8) + (lane & 7)) * 80 + ((ti & 1) * 16);

    // ---- producer assignments ----
    const int arow = tid >> 2, akq = tid & 3;
    const float* aptr = h + (size_t)(tokBase + arow) * D + akq * 8;
    uint32_t* a_sts = su + arow * RS + akq * 4;
    // B: 3 uint4 per thread; flat uint4 index f4 = tid + j*512 -> u32 f = 4*f4
    int b_pl[3], b_su[3];
#pragma unroll
    for (int j = 0; j < 3; ++j) {
        int f = (tid + j * 512) * 4;
        b_pl[j] = f >> 11;
        int rem = f & 2047;
        b_su[j] = (rem >> 4) * RS + (rem & 15);
    }
    uint32_t* b_sts_base = su + (B_BASE_B / 4);

    float4 ra0, ra1;

    // ---- prologue: chunk 0 ----
    ra0 = *(const float4*)(aptr + 0);
    ra1 = *(const float4*)(aptr + 4);
    {
        uint32_t p1[4], p2[4], p3[4];
        split3p(ra0.x, ra0.y, p1[0], p2[0], p3[0]);
        split3p(ra0.z, ra0.w, p1[1], p2[1], p3[1]);
        split3p(ra1.x, ra1.y, p1[2], p2[2], p3[2]);
        split3p(ra1.z, ra1.w, p1[3], p2[3], p3[3]);
        *(uint4*)(a_sts + 0 * PLANE_U32) = make_uint4(p1[0], p1[1], p1[2], p1[3]);
        *(uint4*)(a_sts + 1 * PLANE_U32) = make_uint4(p2[0], p2[1], p2[2], p2[3]);
        *(uint4*)(a_sts + 2 * PLANE_U32) = make_uint4(p3[0], p3[1], p3[2], p3[3]);
        const uint4* bp = (const uint4*)g_Bp;
#pragma unroll
        for (int j = 0; j < 3; ++j) {
            uint4 v = bp[tid + j * 512];
            *(uint4*)(b_sts_base + b_pl[j] * PLANE_U32 + b_su[j]) = v;
        }
    }
    __syncthreads();

    float accM[2][4][4], accC[2][4][4];
#pragma unroll
    for (int mt = 0; mt < 2; ++mt)
#pragma unroll
        for (int nt = 0; nt < 4; ++nt)
#pragma unroll
            for (int j = 0; j < 4; ++j) { accM[mt][nt][j] = 0.f; accC[mt][nt][j] = 0.f; }

    const int NCH = D / KC;   // 32
    for (int s = 0; s < NCH; ++s) {
        const bool more = (s + 1) < NCH;
        if (more) {                       // A prefetch only (8 regs)
            const int off = (s + 1) * KC;
            ra0 = *(const float4*)(aptr + off);
            ra1 = *(const float4*)(aptr + off + 4);
        }

        // ---- consume: 2 k16 steps, term-major MMA order ----
#pragma unroll
        for (int kb = 0; kb < 2; ++kb) {
            uint32_t aa[3][2][4];
#pragma unroll
            for (int p = 0; p < 3; ++p)
#pragma unroll
                for (int mt = 0; mt < 2; ++mt)
                    ldsm4(aa[p][mt],
                          smb + p * 10240 + (mbW + mt * 16) * 80 + kb * 32 + a_off);
            uint32_t bb[3][2][4];
#pragma unroll
            for (int p = 0; p < 3; ++p)
#pragma unroll
                for (int bt = 0; bt < 2; ++bt)
                    ldsm4(bb[p][bt],
                          smb + B_BASE_B + p * 10240 + (nhW + bt * 16) * 80 + kb * 32 + b_off);

            // term-major: each pass = 8 independent MMAs; accC RAW deps are
            // 8 issues apart -> HMMA latency hidden.
#define EMIT_TERM(ACC, PA, PB)                                           \
            _Pragma("unroll")                                            \
            for (int mt = 0; mt < 2; ++mt)                               \
                _Pragma("unroll")                                        \
                for (int bt = 0; bt < 2; ++bt)                           \
                    _Pragma("unroll")                                    \
                    for (int j = 0; j < 2; ++j)                          \
                        mma_bf16(ACC[mt][bt * 2 + j], aa[PA][mt],        \
                                 bb[PB][bt] + 2 * j);
            EMIT_TERM(accM, 0, 0)
            EMIT_TERM(accC, 0, 1)
            EMIT_TERM(accC, 1, 0)
            EMIT_TERM(accC, 0, 2)
            EMIT_TERM(accC, 1, 1)
            EMIT_TERM(accC, 2, 0)
#undef EMIT_TERM
        }
        __syncthreads();

        // ---- produce chunk s+1: A from prefetched regs, B direct L2->smem ----
        if (more) {
            uint32_t p1[4], p2[4], p3[4];
            split3p(ra0.x, ra0.y, p1[0], p2[0], p3[0]);
            split3p(ra0.z, ra0.w, p1[1], p2[1], p3[1]);
            split3p(ra1.x, ra1.y, p1[2], p2[2], p3[2]);
            split3p(ra1.z, ra1.w, p1[3], p2[3], p3[3]);
            *(uint4*)(a_sts + 0 * PLANE_U32) = make_uint4(p1[0], p1[1], p1[2], p1[3]);
            *(uint4*)(a_sts + 1 * PLANE_U32) = make_uint4(p2[0], p2[1], p2[2], p2[3]);
            *(uint4*)(a_sts + 2 * PLANE_U32) = make_uint4(p3[0], p3[1], p3[2], p3[3]);
            const uint4* bp = (const uint4*)(g_Bp + (size_t)(s + 1) * 6144);
#pragma unroll
            for (int j = 0; j < 3; ++j) {
                uint4 v = bp[tid + j * 512];
                *(uint4*)(b_sts_base + b_pl[j] * PLANE_U32 + b_su[j]) = v;
            }
            __syncthreads();
        }
    }

    // ---- merge + dump C to smem (reuses plane region) ----
#pragma unroll
    for (int mt = 0; mt < 2; ++mt)
#pragma unroll
        for (int nt = 0; nt < 4; ++nt) {
            const int r0 = mbW + mt * 16 + g;
            const int c  = nhW + nt * 8 + 2 * t;
            *(float2*)&sf[r0 * CS + c] =
                make_float2(accM[mt][nt][0] + accC[mt][nt][0],
                            accM[mt][nt][1] + accC[mt][nt][1]);
            *(float2*)&sf[(r0 + 8) * CS + c] =
                make_float2(accM[mt][nt][2] + accC[mt][nt][2],
                            accM[mt][nt][3] + accC[mt][nt][3]);
        }
    __syncthreads();

    // ---- epilogue: thread tid<128 handles token tokBase+tid (validated) ----
    if (tid < MROWS) {
        const int tok = tokBase + tid;
        const float* pre = sf + tid * CS;
        const float* nzr = noise + (size_t)tok * E_FIX;

        float noisy[E_FIX];
#pragma unroll
        for (int q = 0; q < E_FIX / 4; ++q) {
            float4 lg = *(const float4*)(pre + 4 * q);
            float4 np = *(const float4*)(pre + E_FIX + 4 * q);
            float4 nv = *(const float4*)(nzr + 4 * q);
            float4 b0 = *(const float4*)(bl + 4 * q);
            float4 b1 = *(const float4*)(bn + 4 * q);
            noisy[4*q+0] = lg.x + b0.x + nv.x * softplus_f(np.x + b1.x);
            noisy[4*q+1] = lg.y + b0.y + nv.y * softplus_f(np.y + b1.y);
            noisy[4*q+2] = lg.z + b0.z + nv.z * softplus_f(np.z + b1.z);
            noisy[4*q+3] = lg.w + b0.w + nv.w * softplus_f(np.w + b1.w);
        }

        float m = noisy[0];
#pragma unroll
        for (int e = 1; e < E_FIX; ++e) m = fmaxf(m, noisy[e]);

        int kidx[8]; float kval[8];
        u64 chosen = 0ull;
        for (int j = 0; j < K; ++j) {
            float best = -INFINITY; int bi = 0;
#pragma unroll
            for (int e = 0; e < E_FIX; ++e) {
                bool ok = (((chosen >> e) & 1ull) == 0ull) && (noisy[e] > best);
                best = ok ? noisy[e] : best;
                bi   = ok ? e : bi;
            }
            kidx[j] = bi; kval[j] = best;
            chosen |= (1ull << bi);
        }

        float sum = 0.0f;
#pragma unroll
        for (int e = 0; e < E_FIX; ++e) { float x = expf(noisy[e] - m); noisy[e] = x; sum += x; }
        const float inv = 1.0f / sum;

        float* route = out + (size_t)tok * E_FIX;
        float* ixo   = out + (size_t)BS * E_FIX + (size_t)tok * K;
        float* fullp = out + (size_t)BS * (E_FIX + K) + (size_t)tok * E_FIX;
#pragma unroll
        for (int q = 0; q < 16; ++q) *(float4*)(route + 4 * q) = make_float4(0.f, 0.f, 0.f, 0.f);
#pragma unroll
        for (int q = 0; q < 16; ++q)
            *(float4*)(fullp + 4 * q) = make_float4(noisy[4*q+0] * inv, noisy[4*q+1] * inv,
                                                    noisy[4*q+2] * inv, noisy[4*q+3] * inv);
        const float rm = kval[0];
        float rs = 0.0f, rv[8];
        for (int j = 0; j < K; ++j) { rv[j] = expf(kval[j] - rm); rs += rv[j]; }
        const float rinv = 1.0f / rs;
        for (int j = 0; j < K; ++j) { route[kidx[j]] = rv[j] * rinv; ixo[j] = (float)kidx[j]; }
    }
}

// ----------------------------------------------------------------------------
// Inputs (metadata order): h, Wl, bl, Wn, bn, noise, [top_k]
// ----------------------------------------------------------------------------
extern "C" void kernel_launch(void* const* d_in, const int* in_sizes, int n_in,
                              void* d_out, int out_size) {
    const float* h  = (const float*)d_in[0];
    const float* Wl = (const float*)d_in[1];
    const float* bl = (const float*)d_in[2];
    const float* Wn = (const float*)d_in[3];
    const float* bn = (const float*)d_in[4];
    const float* nz = (const float*)d_in[5];

    const int E = in_sizes[2];                     // 64
    const int D = in_sizes[1] / E;                 // 1024
    const long long BSE = (long long)in_sizes[5];  // B*S*E
    const int BS = (int)(BSE / E);                 // 32768

    int K = (int)(((long long)out_size - 2LL * BSE) / (long long)BS);
    if (K < 1 || K > 8) K = 2;

    bsplit_kernel<<<128, 512>>>(Wl, Wn, D);
    cudaFuncSetAttribute(router_fused, cudaFuncAttributeMaxDynamicSharedMemorySize, SMEM_BYTES);
    router_fused<<<BS / MROWS, NTHR, SMEM_BYTES>>>(h, bl, bn, nz, (float*)d_out, D, BS, K);
}